// round 2
// baseline (speedup 1.0000x reference)
#include <cuda_runtime.h>
#include <cuda_fp16.h>
#include <cstdint>

#define N_NODES 20000
#define N_EDGES 160000
#define DIM 32          // IN == H == 32
#define EFD 95          // edge feature dim
#define EH 64           // edge hidden
#define NG 64           // graphs
#define ZCOLS 2048      // EH * DIM
#define BN_EPS 1e-5f

// ---------------- scratch (device globals; no runtime allocation) ----------------
__device__ float  g_h[(size_t)N_EDGES * EH];        // 41 MB   relu(edge_attr@W1+b1)
__device__ __half g_Zh[(size_t)N_NODES * ZCOLS];    // 82 MB   Z in fp16, layout [n][o][k]
__device__ float  g_Zb[N_NODES * DIM];              // X @ reshape(b2)
__device__ float  g_agg[N_NODES * DIM];             // scatter-add accumulator
__device__ float  g_x1[N_NODES * DIM];              // conv0 output
__device__ float  g_pool[NG * DIM];                 // global max pool

// ---------------- zero kernels ----------------
__global__ void k_zero_agg() {
    int i = blockIdx.x * blockDim.x + threadIdx.x;
    if (i < N_NODES * DIM) g_agg[i] = 0.f;
}
__global__ void k_zero_pool() {
    int i = blockIdx.x * blockDim.x + threadIdx.x;
    if (i < NG * DIM) g_pool[i] = 0.f;
}

// ---------------- K1: edge MLP  h = relu(EA @ W1 + b1)  [E,64] ----------------
__global__ void k_edge_mlp(const float* __restrict__ ea,
                           const float* __restrict__ W1,
                           const float* __restrict__ b1) {
    __shared__ float W1s[EFD * EH];     // 24320 B
    __shared__ float eas[16 * EFD];     // 6080 B
    __shared__ float b1s[EH];
    int t = threadIdx.x;
    for (int i = t; i < EFD * EH; i += 256) W1s[i] = W1[i];
    if (t < EH) b1s[t] = b1[t];
    int e0 = blockIdx.x * 16;
    for (int i = t; i < 16 * EFD; i += 256) eas[i] = ea[(size_t)e0 * EFD + i];
    __syncthreads();

    int tx = t & 15, ty = t >> 4;      // tx: 4-wide output group, ty: edge
    int e = e0 + ty;
    float4 acc = make_float4(b1s[tx * 4 + 0], b1s[tx * 4 + 1],
                             b1s[tx * 4 + 2], b1s[tx * 4 + 3]);
    const float* ear = &eas[ty * EFD];
#pragma unroll 5
    for (int k = 0; k < EFD; k++) {
        float a = ear[k];
        float4 w = *(const float4*)&W1s[k * EH + tx * 4];
        acc.x = fmaf(a, w.x, acc.x);
        acc.y = fmaf(a, w.y, acc.y);
        acc.z = fmaf(a, w.z, acc.z);
        acc.w = fmaf(a, w.w, acc.w);
    }
    float4 r = make_float4(fmaxf(acc.x, 0.f), fmaxf(acc.y, 0.f),
                           fmaxf(acc.z, 0.f), fmaxf(acc.w, 0.f));
    *(float4*)&g_h[(size_t)e * EH + tx * 4] = r;
}

// ---------------- K2: Zh[n, o*64+k] = sum_i X[n,i] * W2[k*1024 + i*32 + o] ----------
// tile: 64 nodes x 64 cols, 256 threads, each thread 4x4, fp16 output.
__global__ void __launch_bounds__(256) k_zgemm(const float* __restrict__ X,
                                               const float* __restrict__ W2) {
    __shared__ float Xs[64 * DIM];      // 8 KB
    __shared__ float Bs[DIM * 64];      // 8 KB
    int t = threadIdx.x;
    int n0 = blockIdx.y * 64;
    int c0 = blockIdx.x * 64;

    for (int i = t; i < 64 * DIM; i += 256) {
        int n = n0 + (i >> 5);
        Xs[i] = (n < N_NODES) ? X[(size_t)n * DIM + (i & 31)] : 0.f;
    }
    for (int i = t; i < DIM * 64; i += 256) {
        int row = i >> 6;               // x-input index i
        int c = c0 + (i & 63);          // flat Z col in [n][o][k]: o = c>>6, k = c&63
        Bs[i] = W2[(c & 63) * 1024 + row * DIM + (c >> 6)];
    }
    __syncthreads();

    int tcol = t & 15, trow = t >> 4;   // 16 x 16 threads, 4x4 each
    float acc[4][4] = {};
#pragma unroll
    for (int i = 0; i < DIM; i++) {
        float4 bv = *(const float4*)&Bs[i * 64 + tcol * 4];
#pragma unroll
        for (int r = 0; r < 4; r++) {
            float a = Xs[(trow * 4 + r) * DIM + i];   // warp-broadcast LDS
            acc[r][0] = fmaf(a, bv.x, acc[r][0]);
            acc[r][1] = fmaf(a, bv.y, acc[r][1]);
            acc[r][2] = fmaf(a, bv.z, acc[r][2]);
            acc[r][3] = fmaf(a, bv.w, acc[r][3]);
        }
    }
#pragma unroll
    for (int r = 0; r < 4; r++) {
        int n = n0 + trow * 4 + r;
        if (n < N_NODES) {
            __half2 h0 = __floats2half2_rn(acc[r][0], acc[r][1]);
            __half2 h1 = __floats2half2_rn(acc[r][2], acc[r][3]);
            uint2 pk = make_uint2(*(uint32_t*)&h0, *(uint32_t*)&h1);
            *(uint2*)&g_Zh[(size_t)n * ZCOLS + c0 + tcol * 4] = pk;
        }
    }
}

// ---------------- K2b: Zb[n,o] = sum_i X[n,i] * b2[i*32+o] ----------------
__global__ void k_zb(const float* __restrict__ X, const float* __restrict__ b2) {
    __shared__ float Bs[DIM * DIM];
    int t = threadIdx.x;
    for (int i = t; i < DIM * DIM; i += 256) Bs[i] = b2[i];
    __syncthreads();
    int n = blockIdx.x * 8 + (t >> 5);
    int o = t & 31;
    const float* xr = X + (size_t)n * DIM;
    float v = 0.f;
#pragma unroll
    for (int i = 0; i < DIM; i++) v = fmaf(xr[i], Bs[i * DIM + o], v);
    g_Zb[n * DIM + o] = v;
}

// ---------------- K3: edge combine + scatter-add ----------------
// warp per edge; lane = output channel o.
// msg[o] = Zb[src,o] + sum_k h[e,k] * Zh[src, o*64+k]   (k contiguous -> LDG.128)
__global__ void k_scatter(const int* __restrict__ src, const int* __restrict__ dst) {
    __shared__ float hsh[8 * EH];       // 8 edges/block
    int t = threadIdx.x;
    size_t hbase = (size_t)blockIdx.x * (8 * EH);
    hsh[t] = g_h[hbase + t];
    hsh[t + 256] = g_h[hbase + t + 256];
    __syncthreads();

    int wid = t >> 5, lane = t & 31;
    int e = blockIdx.x * 8 + wid;
    int s = src[e], d = dst[e];
    const __half* zr = g_Zh + (size_t)s * ZCOLS + lane * EH;   // 128B-aligned row
    const float* hr = &hsh[wid * EH];
    float msg = g_Zb[s * DIM + lane];
#pragma unroll
    for (int j = 0; j < 8; j++) {
        uint4 v = __ldg((const uint4*)(zr + j * 8));           // 8 halves
        float2 p0 = __half22float2(*(__half2*)&v.x);
        float2 p1 = __half22float2(*(__half2*)&v.y);
        float2 p2 = __half22float2(*(__half2*)&v.z);
        float2 p3 = __half22float2(*(__half2*)&v.w);
        msg = fmaf(hr[j * 8 + 0], p0.x, msg);
        msg = fmaf(hr[j * 8 + 1], p0.y, msg);
        msg = fmaf(hr[j * 8 + 2], p1.x, msg);
        msg = fmaf(hr[j * 8 + 3], p1.y, msg);
        msg = fmaf(hr[j * 8 + 4], p2.x, msg);
        msg = fmaf(hr[j * 8 + 5], p2.y, msg);
        msg = fmaf(hr[j * 8 + 6], p3.x, msg);
        msg = fmaf(hr[j * 8 + 7], p3.y, msg);
    }
    atomicAdd(&g_agg[d * DIM + lane], msg);
}

// ---------------- K4: node update (root GEMM + bias + BN + relu) ----------------
template <bool POOL>
__global__ void k_node_update(const float* __restrict__ xin,
                              const float* __restrict__ root,
                              const float* __restrict__ bias,
                              const float* __restrict__ bng,
                              const float* __restrict__ bnb,
                              const float* __restrict__ bnrm,
                              const float* __restrict__ bnrv,
                              float* __restrict__ xout,
                              const int* __restrict__ batch) {
    __shared__ float Rs[DIM * DIM];
    int t = threadIdx.x;
    for (int i = t; i < DIM * DIM; i += 256) Rs[i] = root[i];
    __syncthreads();
    int n = blockIdx.x * 8 + (t >> 5);
    int o = t & 31;
    const float* xr = xin + (size_t)n * DIM;
    float v = g_agg[n * DIM + o] + bias[o];
#pragma unroll
    for (int i = 0; i < DIM; i++) v = fmaf(xr[i], Rs[i * DIM + o], v);
    v = (v - bnrm[o]) * rsqrtf(bnrv[o] + BN_EPS) * bng[o] + bnb[o];
    v = fmaxf(v, 0.f);
    if (POOL) {
        int b = batch[n];
        atomicMax((int*)&g_pool[b * DIM + o], __float_as_int(v));
    } else {
        xout[n * DIM + o] = v;
    }
}

// ---------------- K6: head  out = relu(pool @ lin1 + b) @ lin2 + b2 ----------------
__global__ void k_head(const float* __restrict__ l1W, const float* __restrict__ l1b,
                       const float* __restrict__ l2W, const float* __restrict__ l2b,
                       float* __restrict__ out) {
    int g = threadIdx.x;                 // 64 graphs, 64 threads
    const float* pr = &g_pool[g * DIM];
    float tbuf[DIM];
#pragma unroll
    for (int j = 0; j < DIM; j++) {
        float v = l1b[j];
#pragma unroll
        for (int i = 0; i < DIM; i++) v = fmaf(pr[i], l1W[i * DIM + j], v);
        tbuf[j] = fmaxf(v, 0.f);
    }
#pragma unroll
    for (int c = 0; c < 2; c++) {
        float v = l2b[c];
#pragma unroll
        for (int j = 0; j < DIM; j++) v = fmaf(tbuf[j], l2W[j * 2 + c], v);
        out[g * 2 + c] = v;
    }
}

// ---------------- launch ----------------
extern "C" void kernel_launch(void* const* d_in, const int* in_sizes, int n_in,
                              void* d_out, int out_size) {
    const float* x     = (const float*)d_in[0];
    const int*   esrc  = (const int*)d_in[1];
    const int*   edst  = (const int*)d_in[2];
    const float* ea    = (const float*)d_in[3];
    const int*   batch = (const int*)d_in[4];

    const float* c0W1 = (const float*)d_in[5];
    const float* c0b1 = (const float*)d_in[6];
    const float* c0W2 = (const float*)d_in[7];
    const float* c0b2 = (const float*)d_in[8];
    const float* c0rt = (const float*)d_in[9];
    const float* c0bs = (const float*)d_in[10];
    const float* bn0g = (const float*)d_in[11];
    const float* bn0b = (const float*)d_in[12];
    const float* bn0m = (const float*)d_in[13];
    const float* bn0v = (const float*)d_in[14];

    const float* c1W1 = (const float*)d_in[15];
    const float* c1b1 = (const float*)d_in[16];
    const float* c1W2 = (const float*)d_in[17];
    const float* c1b2 = (const float*)d_in[18];
    const float* c1rt = (const float*)d_in[19];
    const float* c1bs = (const float*)d_in[20];
    const float* bn1g = (const float*)d_in[21];
    const float* bn1b = (const float*)d_in[22];
    const float* bn1m = (const float*)d_in[23];
    const float* bn1v = (const float*)d_in[24];

    const float* l1W = (const float*)d_in[25];
    const float* l1b = (const float*)d_in[26];
    const float* l2W = (const float*)d_in[27];
    const float* l2b = (const float*)d_in[28];

    float* out = (float*)d_out;

    void* px1 = nullptr;
    cudaGetSymbolAddress(&px1, g_x1);
    float* x1 = (float*)px1;

    dim3 zg(ZCOLS / 64, (N_NODES + 63) / 64);   // 32 x 313

    // ---- conv0 ----
    k_zero_agg<<<(N_NODES * DIM + 255) / 256, 256>>>();
    k_zero_pool<<<(NG * DIM + 255) / 256, 256>>>();
    k_edge_mlp<<<N_EDGES / 16, 256>>>(ea, c0W1, c0b1);
    k_zgemm<<<zg, 256>>>(x, c0W2);
    k_zb<<<N_NODES / 8, 256>>>(x, c0b2);
    k_scatter<<<N_EDGES / 8, 256>>>(esrc, edst);
    k_node_update<false><<<N_NODES / 8, 256>>>(x, c0rt, c0bs, bn0g, bn0b, bn0m, bn0v,
                                               x1, nullptr);

    // ---- conv1 ----
    k_zero_agg<<<(N_NODES * DIM + 255) / 256, 256>>>();
    k_edge_mlp<<<N_EDGES / 16, 256>>>(ea, c1W1, c1b1);
    k_zgemm<<<zg, 256>>>(x1, c1W2);
    k_zb<<<N_NODES / 8, 256>>>(x1, c1b2);
    k_scatter<<<N_EDGES / 8, 256>>>(esrc, edst);
    k_node_update<true><<<N_NODES / 8, 256>>>(x1, c1rt, c1bs, bn1g, bn1b, bn1m, bn1v,
                                              nullptr, batch);

    // ---- head ----
    k_head<<<1, NG>>>(l1W, l1b, l2W, l2b, out);
}

// round 3
// speedup vs baseline: 1.5717x; 1.5717x over previous
#include <cuda_runtime.h>
#include <cuda_fp16.h>
#include <cstdint>

#define N_NODES 20000
#define N_EDGES 160000
#define DIM 32          // IN == H == 32
#define EFD 95          // edge feature dim
#define EH 64           // edge hidden
#define NG 64           // graphs
#define ZCOLS 2048      // EH * DIM
#define BN_EPS 1e-5f

// ---------------- scratch (device globals; no runtime allocation) ----------------
__device__ float  g_h[(size_t)N_EDGES * EH];                    // 41 MB
// Z in fp16, layout [n][kb][o][r]: flat col = kb*256 + o*8 + r, k = kb*8+r
__device__ __align__(16) __half g_Zh[(size_t)N_NODES * ZCOLS];  // 82 MB
__device__ float  g_Zb[N_NODES * DIM];
__device__ float  g_agg[N_NODES * DIM];
__device__ float  g_x1[N_NODES * DIM];
__device__ float  g_pool[NG * DIM];

// ---------------- zero kernels ----------------
__global__ void k_zero_agg() {
    int i = blockIdx.x * blockDim.x + threadIdx.x;
    if (i < N_NODES * DIM) g_agg[i] = 0.f;
}
__global__ void k_zero_pool() {
    int i = blockIdx.x * blockDim.x + threadIdx.x;
    if (i < NG * DIM) g_pool[i] = 0.f;
}

// ---------------- K1: edge MLP  h = relu(EA @ W1 + b1)  [E,64] ----------------
__global__ void k_edge_mlp(const float* __restrict__ ea,
                           const float* __restrict__ W1,
                           const float* __restrict__ b1) {
    __shared__ float W1s[EFD * EH];     // 24320 B
    __shared__ float eas[16 * EFD];     // 6080 B
    __shared__ float b1s[EH];
    int t = threadIdx.x;
    for (int i = t; i < EFD * EH; i += 256) W1s[i] = W1[i];
    if (t < EH) b1s[t] = b1[t];
    int e0 = blockIdx.x * 16;
    for (int i = t; i < 16 * EFD; i += 256) eas[i] = ea[(size_t)e0 * EFD + i];
    __syncthreads();

    int tx = t & 15, ty = t >> 4;
    int e = e0 + ty;
    float4 acc = make_float4(b1s[tx * 4 + 0], b1s[tx * 4 + 1],
                             b1s[tx * 4 + 2], b1s[tx * 4 + 3]);
    const float* ear = &eas[ty * EFD];
#pragma unroll 5
    for (int k = 0; k < EFD; k++) {
        float a = ear[k];
        float4 w = *(const float4*)&W1s[k * EH + tx * 4];
        acc.x = fmaf(a, w.x, acc.x);
        acc.y = fmaf(a, w.y, acc.y);
        acc.z = fmaf(a, w.z, acc.z);
        acc.w = fmaf(a, w.w, acc.w);
    }
    float4 r = make_float4(fmaxf(acc.x, 0.f), fmaxf(acc.y, 0.f),
                           fmaxf(acc.z, 0.f), fmaxf(acc.w, 0.f));
    *(float4*)&g_h[(size_t)e * EH + tx * 4] = r;
}

// ---------------- K2: Zh[n][kb][o][r] = sum_i X[n,i] * W2[(kb*8+r)*1024 + i*32 + o] --
// block: 32 nodes x one kb-block (256 packed cols). 256 threads = 32 o x 8 trow.
// Each thread: 4 nodes x 8 r accumulators. W2 tile load is a linear coalesced copy.
__global__ void __launch_bounds__(256) k_zgemm(const float* __restrict__ X,
                                               const float* __restrict__ W2) {
    __shared__ float Xs[32 * DIM];      // 4 KB
    __shared__ float Bs[8 * 32 * 32];   // 32 KB, Bs[r*1024 + i*32 + o]
    int t = threadIdx.x;
    int kb = blockIdx.x;                // 0..7
    int n0 = blockIdx.y * 32;           // 20000 % 32 == 0

    for (int i = t; i < 32 * DIM; i += 256)
        Xs[i] = X[(size_t)n0 * DIM + i];
    const float* w2src = W2 + (size_t)kb * 8192;
#pragma unroll
    for (int i = 0; i < 8192; i += 256)
        Bs[i + t] = w2src[i + t];
    __syncthreads();

    int o = t & 31, trow = t >> 5;      // trow: 0..7, 4 nodes each
    float acc[4][8] = {};
#pragma unroll
    for (int i = 0; i < DIM; i++) {
        float b[8];
#pragma unroll
        for (int r = 0; r < 8; r++) b[r] = Bs[r * 1024 + i * 32 + o];
#pragma unroll
        for (int rr = 0; rr < 4; rr++) {
            float a = Xs[(trow * 4 + rr) * DIM + i];
#pragma unroll
            for (int r = 0; r < 8; r++)
                acc[rr][r] = fmaf(a, b[r], acc[rr][r]);
        }
    }
#pragma unroll
    for (int rr = 0; rr < 4; rr++) {
        int n = n0 + trow * 4 + rr;
        __half2 p0 = __floats2half2_rn(acc[rr][0], acc[rr][1]);
        __half2 p1 = __floats2half2_rn(acc[rr][2], acc[rr][3]);
        __half2 p2 = __floats2half2_rn(acc[rr][4], acc[rr][5]);
        __half2 p3 = __floats2half2_rn(acc[rr][6], acc[rr][7]);
        uint4 pk = make_uint4(*(uint32_t*)&p0, *(uint32_t*)&p1,
                              *(uint32_t*)&p2, *(uint32_t*)&p3);
        *(uint4*)&g_Zh[(size_t)n * ZCOLS + kb * 256 + o * 8] = pk;
    }
}

// ---------------- K2b: Zb[n,o] = sum_i X[n,i] * b2[i*32+o] ----------------
__global__ void k_zb(const float* __restrict__ X, const float* __restrict__ b2) {
    __shared__ float Bs[DIM * DIM];
    int t = threadIdx.x;
    for (int i = t; i < DIM * DIM; i += 256) Bs[i] = b2[i];
    __syncthreads();
    int n = blockIdx.x * 8 + (t >> 5);
    int o = t & 31;
    const float* xr = X + (size_t)n * DIM;
    float v = 0.f;
#pragma unroll
    for (int i = 0; i < DIM; i++) v = fmaf(xr[i], Bs[i * DIM + o], v);
    g_Zb[n * DIM + o] = v;
}

// ---------------- K3: edge combine + scatter-add ----------------
// warp per edge; lane = output channel o.
// msg[o] = Zb[src,o] + sum_kb sum_r h[kb*8+r] * Zh[src][kb][o][r]
// Each uint4 load: warp reads contiguous 512B (4 lines) -> coalesced.
__global__ void k_scatter(const int* __restrict__ src, const int* __restrict__ dst) {
    __shared__ float hsh[8 * EH];       // 8 edges/block
    int t = threadIdx.x;
    size_t hbase = (size_t)blockIdx.x * (8 * EH);
    hsh[t] = g_h[hbase + t];
    hsh[t + 256] = g_h[hbase + t + 256];
    __syncthreads();

    int wid = t >> 5, lane = t & 31;
    int e = blockIdx.x * 8 + wid;
    int s = src[e], d = dst[e];
    const __half* zr = g_Zh + (size_t)s * ZCOLS + lane * 8;
    const float* hr = &hsh[wid * EH];
    float msg = g_Zb[s * DIM + lane];
#pragma unroll
    for (int kb = 0; kb < 8; kb++) {
        uint4 v = __ldg((const uint4*)(zr + kb * 256));        // 8 halves, r=0..7
        float2 p0 = __half22float2(*(__half2*)&v.x);
        float2 p1 = __half22float2(*(__half2*)&v.y);
        float2 p2 = __half22float2(*(__half2*)&v.z);
        float2 p3 = __half22float2(*(__half2*)&v.w);
        msg = fmaf(hr[kb * 8 + 0], p0.x, msg);
        msg = fmaf(hr[kb * 8 + 1], p0.y, msg);
        msg = fmaf(hr[kb * 8 + 2], p1.x, msg);
        msg = fmaf(hr[kb * 8 + 3], p1.y, msg);
        msg = fmaf(hr[kb * 8 + 4], p2.x, msg);
        msg = fmaf(hr[kb * 8 + 5], p2.y, msg);
        msg = fmaf(hr[kb * 8 + 6], p3.x, msg);
        msg = fmaf(hr[kb * 8 + 7], p3.y, msg);
    }
    atomicAdd(&g_agg[d * DIM + lane], msg);
}

// ---------------- K4: node update (root GEMM + bias + BN + relu) ----------------
template <bool POOL>
__global__ void k_node_update(const float* __restrict__ xin,
                              const float* __restrict__ root,
                              const float* __restrict__ bias,
                              const float* __restrict__ bng,
                              const float* __restrict__ bnb,
                              const float* __restrict__ bnrm,
                              const float* __restrict__ bnrv,
                              float* __restrict__ xout,
                              const int* __restrict__ batch) {
    __shared__ float Rs[DIM * DIM];
    int t = threadIdx.x;
    for (int i = t; i < DIM * DIM; i += 256) Rs[i] = root[i];
    __syncthreads();
    int n = blockIdx.x * 8 + (t >> 5);
    int o = t & 31;
    const float* xr = xin + (size_t)n * DIM;
    float v = g_agg[n * DIM + o] + bias[o];
#pragma unroll
    for (int i = 0; i < DIM; i++) v = fmaf(xr[i], Rs[i * DIM + o], v);
    v = (v - bnrm[o]) * rsqrtf(bnrv[o] + BN_EPS) * bng[o] + bnb[o];
    v = fmaxf(v, 0.f);
    if (POOL) {
        int b = batch[n];
        atomicMax((int*)&g_pool[b * DIM + o], __float_as_int(v));
    } else {
        xout[n * DIM + o] = v;
    }
}

// ---------------- K6: head ----------------
__global__ void k_head(const float* __restrict__ l1W, const float* __restrict__ l1b,
                       const float* __restrict__ l2W, const float* __restrict__ l2b,
                       float* __restrict__ out) {
    int g = threadIdx.x;
    const float* pr = &g_pool[g * DIM];
    float tbuf[DIM];
#pragma unroll
    for (int j = 0; j < DIM; j++) {
        float v = l1b[j];
#pragma unroll
        for (int i = 0; i < DIM; i++) v = fmaf(pr[i], l1W[i * DIM + j], v);
        tbuf[j] = fmaxf(v, 0.f);
    }
#pragma unroll
    for (int c = 0; c < 2; c++) {
        float v = l2b[c];
#pragma unroll
        for (int j = 0; j < DIM; j++) v = fmaf(tbuf[j], l2W[j * 2 + c], v);
        out[g * 2 + c] = v;
    }
}

// ---------------- launch ----------------
extern "C" void kernel_launch(void* const* d_in, const int* in_sizes, int n_in,
                              void* d_out, int out_size) {
    const float* x     = (const float*)d_in[0];
    const int*   esrc  = (const int*)d_in[1];
    const int*   edst  = (const int*)d_in[2];
    const float* ea    = (const float*)d_in[3];
    const int*   batch = (const int*)d_in[4];

    const float* c0W1 = (const float*)d_in[5];
    const float* c0b1 = (const float*)d_in[6];
    const float* c0W2 = (const float*)d_in[7];
    const float* c0b2 = (const float*)d_in[8];
    const float* c0rt = (const float*)d_in[9];
    const float* c0bs = (const float*)d_in[10];
    const float* bn0g = (const float*)d_in[11];
    const float* bn0b = (const float*)d_in[12];
    const float* bn0m = (const float*)d_in[13];
    const float* bn0v = (const float*)d_in[14];

    const float* c1W1 = (const float*)d_in[15];
    const float* c1b1 = (const float*)d_in[16];
    const float* c1W2 = (const float*)d_in[17];
    const float* c1b2 = (const float*)d_in[18];
    const float* c1rt = (const float*)d_in[19];
    const float* c1bs = (const float*)d_in[20];
    const float* bn1g = (const float*)d_in[21];
    const float* bn1b = (const float*)d_in[22];
    const float* bn1m = (const float*)d_in[23];
    const float* bn1v = (const float*)d_in[24];

    const float* l1W = (const float*)d_in[25];
    const float* l1b = (const float*)d_in[26];
    const float* l2W = (const float*)d_in[27];
    const float* l2b = (const float*)d_in[28];

    float* out = (float*)d_out;

    void* px1 = nullptr;
    cudaGetSymbolAddress(&px1, g_x1);
    float* x1 = (float*)px1;

    dim3 zg(8, N_NODES / 32);           // 8 kb-blocks x 625 node tiles

    // ---- conv0 ----
    k_zero_agg<<<(N_NODES * DIM + 255) / 256, 256>>>();
    k_zero_pool<<<(NG * DIM + 255) / 256, 256>>>();
    k_edge_mlp<<<N_EDGES / 16, 256>>>(ea, c0W1, c0b1);
    k_zgemm<<<zg, 256>>>(x, c0W2);
    k_zb<<<N_NODES / 8, 256>>>(x, c0b2);
    k_scatter<<<N_EDGES / 8, 256>>>(esrc, edst);
    k_node_update<false><<<N_NODES / 8, 256>>>(x, c0rt, c0bs, bn0g, bn0b, bn0m, bn0v,
                                               x1, nullptr);

    // ---- conv1 ----
    k_zero_agg<<<(N_NODES * DIM + 255) / 256, 256>>>();
    k_edge_mlp<<<N_EDGES / 16, 256>>>(ea, c1W1, c1b1);
    k_zgemm<<<zg, 256>>>(x1, c1W2);
    k_zb<<<N_NODES / 8, 256>>>(x1, c1b2);
    k_scatter<<<N_EDGES / 8, 256>>>(esrc, edst);
    k_node_update<true><<<N_NODES / 8, 256>>>(x1, c1rt, c1bs, bn1g, bn1b, bn1m, bn1v,
                                              nullptr, batch);

    // ---- head ----
    k_head<<<1, NG>>>(l1W, l1b, l2W, l2b, out);
}